// round 13
// baseline (speedup 1.0000x reference)
#include <cuda_runtime.h>
#include <math.h>

// Problem constants
#define BB 4
#define HH 200
#define WW 176
#define HW (HH*WW)         // 35200
#define FA 10
#define NF 5
#define NFR (BB*NF)        // 20 (b,frame) pairs
#define NPF (HW*2)         // 70400 elements per frame
#define NPOS (BB*HW)       // 140800 positions; NPOS/2 = 70400 = 275*256 exactly
#define EPSV 1e-6f
#define NBIN 4096
#define CAP 4096
#define SBLK 69            // blocks per frame in k_sumfin (69*256 >= NPF/4=17600)
#define PLCAP 512

// ---- scratch (device globals; zero-initialized at load; self-cleaning) ----
__device__ float  g_vbuf[BB*NF*NPF];   // masked psm logits, 5.6MB
__device__ int    g_hist[NFR*NBIN];    // 12-bit-prefix histograms
__device__ int    g_pcnt[NFR];
__device__ float  g_cbuf[NFR*CAP];     // threshold-bin candidates
__device__ int    g_ccount[NFR];
__device__ int    g_fdone[NFR];        // per-frame arrival counters
__device__ int    g_Pv[NFR], g_Rv[NFR];
__device__ double g_clspos, g_huber, g_num;
__device__ int    g_fin_done;

// monotonic float<->uint key mapping (ascending)
__device__ __forceinline__ unsigned kmap(float x){
    unsigned u = __float_as_uint(x);
    return (u & 0x80000000u) ? ~u : (u | 0x80000000u);
}
__device__ __forceinline__ float kunmap(unsigned m){
    unsigned u = (m & 0x80000000u) ? (m & 0x7FFFFFFFu) : ~m;
    return __uint_as_float(u);
}
// neg-class loss from raw logit (monotone non-decreasing in x => top-k by x == top-k by v)
__device__ __forceinline__ float vneg(float x){
    float pp = 1.0f/(1.0f + expf(-x));
    return -logf(1.0f - pp + EPSV);
}
__device__ __forceinline__ double wredd(double v){
    #pragma unroll
    for (int o=16;o;o>>=1) v += __shfl_down_sync(0xffffffffu, v, o);
    return v;
}

// hierarchical suffix scan over shared hist[NBIN], T threads.
template<int T>
__device__ __forceinline__ void scan_pick(int* hist, int* Sc, int* Sw,
                                          int k, int* oP, int* oR, int tid)
{
    const int C = NBIN/T;
    int s = 0;
    #pragma unroll
    for (int j=0;j<C;j++) s += hist[tid*C + j];
    Sc[tid] = s;
    int ws = s;
    #pragma unroll
    for (int o=16;o;o>>=1) ws += __shfl_down_sync(0xffffffffu, ws, o);
    if ((tid & 31) == 0) Sw[tid >> 5] = ws;
    __syncthreads();
    if (tid == 0){
        const int NW = T/32;
        int cum = 0, w = NW-1;
        while (w > 0 && cum + Sw[w] < k){ cum += Sw[w]; w--; }
        int c = w*32 + 31;
        while (c > w*32 && cum + Sc[c] < k){ cum += Sc[c]; c--; }
        int b = c*C + C-1;
        while (b > c*C && cum + hist[b] < k){ cum += hist[b]; b--; }
        *oP = b; *oR = k - cum;
    }
    __syncthreads();
}

// ---------- main pass: 2 positions/thread, grid 275 x 256, exact cover ----------
__global__ void __launch_bounds__(256) k_main(
    const float* __restrict__ rm,  const float* __restrict__ psm,
    const float* __restrict__ pos, const float* __restrict__ neg,
    const float* __restrict__ tgt)
{
    __shared__ double sD[8];
    __shared__ int s_pcount;
    __shared__ int s_plist[PLCAP];
    int tid = threadIdx.x;
    if (tid == 0) s_pcount = 0;
    __syncthreads();

    int i  = blockIdx.x*256 + tid;       // pair index 0..70399, exact
    int g0 = 2*i;                        // first of two positions (same batch: HW even)
    int b  = g0 / HW, p0 = g0 - b*HW;

    // ---- front-load ALL 20 independent loads ----
    const float4* pp4 = (const float4*)(pos + (size_t)g0*FA);   // 20 floats, 16B aligned
    const float4* nn4 = (const float4*)(neg + (size_t)g0*FA);
    float4 pv[5], nv[5];
    #pragma unroll
    for (int j=0;j<5;j++){ pv[j] = pp4[j]; nv[j] = nn4[j]; }
    float2 xs[FA];
    #pragma unroll
    for (int a=0;a<FA;a++)
        xs[a] = *(const float2*)(psm + ((size_t)(b*FA + a))*HW + p0);

    // ---- collapse pos/neg to bitmasks (flat = q*10 + a, q = position 0/1) ----
    unsigned nmask = 0, pmask = 0;
    #pragma unroll
    for (int j=0;j<5;j++){
        float pe[4] = {pv[j].x, pv[j].y, pv[j].z, pv[j].w};
        float ne[4] = {nv[j].x, nv[j].y, nv[j].z, nv[j].w};
        #pragma unroll
        for (int e=0;e<4;e++){
            int flat = 4*j + e;
            if (ne[e] != 0.0f) nmask |= 1u << flat;
            if (pe[e] != 0.0f) pmask |= 1u << flat;
        }
    }

    // ---- hist REDG + masked vbuf stores (float4 per frame) ----
    #pragma unroll
    for (int a=0;a<FA;a++){
        bool n0 = (nmask >> a)      & 1u;
        bool n1 = (nmask >> (10+a)) & 1u;
        int base = (b*NF + (a>>1)) << 12;
        if (n0) atomicAdd(&g_hist[base + (int)(kmap(xs[a].x) >> 20)], 1);
        if (n1) atomicAdd(&g_hist[base + (int)(kmap(xs[a].y) >> 20)], 1);
    }
    const float QNAN = __int_as_float(0x7FC00000);
    #pragma unroll
    for (int f=0; f<NF; f++){
        int a0 = 2*f, a1 = 2*f+1;
        float4 w;
        w.x = ((nmask >> a0)      & 1u) ? xs[a0].x : QNAN;   // (p0  , a0)
        w.y = ((nmask >> a1)      & 1u) ? xs[a1].x : QNAN;   // (p0  , a1)
        w.z = ((nmask >> (10+a0)) & 1u) ? xs[a0].y : QNAN;   // (p0+1, a0)
        w.w = ((nmask >> (10+a1)) & 1u) ? xs[a1].y : QNAN;   // (p0+1, a1)
        *(float4*)(g_vbuf + ((size_t)(b*NF+f))*NPF + (size_t)p0*2) = w;
    }

    // ---- append positives to shared list (rare: ~26/block) ----
    unsigned pm = pmask;
    while (pm){
        int flat = __ffs(pm) - 1; pm &= pm - 1;
        int id = atomicAdd(&s_pcount, 1);
        if (id < PLCAP) s_plist[id] = (tid << 5) | flat;
    }
    __syncthreads();

    // ---- cooperative positive processing ----
    int cnt = s_pcount; if (cnt > PLCAP) cnt = PLCAP;
    double l_cp = 0.0, l_hb = 0.0;
    for (int e = tid; e < cnt; e += 256){
        int pk = s_plist[e];
        int lt = pk >> 5, flat = pk & 31;
        int q = flat / 10, a = flat - 10*q;
        int gg = 2*(blockIdx.x*256 + lt) + q;
        int bb = gg / HW, pp = gg - bb*HW;
        atomicAdd(&g_pcnt[bb*NF + (a>>1)], 1);
        float x = psm[((size_t)(bb*FA + a))*HW + pp];
        float s = 1.0f/(1.0f + expf(-x));
        l_cp -= (double)logf(s + EPSV);
        const float* tp = tgt + ((size_t)gg*(FA*7) + a*7);
        const float* rp = rm  + ((size_t)(bb*FA*7) + a*7)*HW + pp;
        #pragma unroll
        for (int j=0;j<7;j++){
            float d = fabsf(rp[(size_t)j*HW] - tp[j]);
            l_hb += (d < 1.0f) ? (double)(0.5f*d*d) : (double)(d - 0.5f);
        }
    }

    // block-reduce the two double sums (skip global atomic if zero)
    int lane = tid & 31, wd = tid >> 5;
    double r1 = wredd(l_cp);
    if (lane==0) sD[wd] = r1;
    __syncthreads();
    if (wd==0){
        double a = (lane<8)? sD[lane] : 0.0;
        a = wredd(a);
        if (lane==0 && a != 0.0) atomicAdd(&g_clspos, a);
    }
    __syncthreads();
    double r2 = wredd(l_hb);
    if (lane==0) sD[wd] = r2;
    __syncthreads();
    if (wd==0){
        double a = (lane<8)? sD[lane] : 0.0;
        a = wredd(a);
        if (lane==0 && a != 0.0) atomicAdd(&g_huber, a);
    }
}

// ---------------- per-frame threshold pick: 20 x 512 ----------------
__global__ void __launch_bounds__(512) k_scan(){
    __shared__ int hist[NBIN];
    __shared__ int Sc[512];
    __shared__ int Sw[16];
    __shared__ int sP, sR;
    int f = blockIdx.x, tid = threadIdx.x;
    for (int i=tid; i<NBIN/4; i+=512){
        int4 h = ((const int4*)(g_hist + (f<<12)))[i];
        hist[4*i]=h.x; hist[4*i+1]=h.y; hist[4*i+2]=h.z; hist[4*i+3]=h.w;
        ((int4*)(g_hist + (f<<12)))[i] = make_int4(0,0,0,0);   // self-clean
    }
    __syncthreads();
    int k = 3*(g_pcnt[f] + 1);                // floor(3*(cnt+1)) exactly
    scan_pick<512>(hist, Sc, Sw, k, &sP, &sR, tid);
    if (tid == 0){ g_Pv[f] = sP; g_Rv[f] = sR; }
}

// ------- fused plane pass + per-frame last-block refine: grid (SBLK,NFR) x 256 -------
__global__ void __launch_bounds__(256) k_sumfin(float* __restrict__ out){
    __shared__ int hist[NBIN];                // used only by last block of frame
    __shared__ int Sc[256];
    __shared__ int Sw[8];
    __shared__ float cand2[256];
    __shared__ double sD[8];
    __shared__ int sP, sR, s_m, s_cgt, s_last, s_gl;
    __shared__ unsigned s_tk;

    int f = blockIdx.y, tid = threadIdx.x;
    int lane = tid & 31, wd = tid >> 5;
    int P = g_Pv[f];                          // precomputed by k_scan

    // plane pass chunk: sum v(x) above-bin, stash in-bin candidates
    double acc = 0.0;
    int i = blockIdx.x*256 + tid;
    if (i < NPF/4){
        float4 q = ((const float4*)(g_vbuf + (size_t)f*NPF))[i];
        float xv[4] = {q.x, q.y, q.z, q.w};
        #pragma unroll
        for (int j=0;j<4;j++){
            float x = xv[j];
            if (x == x){                        // not NaN => neg==1 anchor
                int t = (int)(kmap(x) >> 20);
                if (t > P) acc += (double)vneg(x);
                else if (t == P){
                    int id = atomicAdd(&g_ccount[f], 1);
                    if (id < CAP) g_cbuf[f*CAP + id] = x;
                }
            }
        }
    }
    {   // block-reduce acc -> g_num, then per-frame arrival
        double r = wredd(acc);
        if (lane==0) sD[wd] = r;
        __syncthreads();
        if (wd==0){
            double a = (lane<8)? sD[lane] : 0.0;
            a = wredd(a);
            if (lane==0){
                if (a != 0.0) atomicAdd(&g_num, a);
                __threadfence();
                int old = atomicAdd(&g_fdone[f], 1);
                s_last = (old == SBLK-1);
            }
        }
    }
    __syncthreads();
    if (!s_last) return;                        // 68 of 69 blocks exit here
    __threadfence();                            // acquire all frame writes

    // ---- last block of frame f: level-2 refinement ----
    int n = *((volatile int*)&g_ccount[f]); if (n > CAP) n = CAP;
    int R = g_Rv[f];
    for (int j=tid; j<NBIN; j+=256) hist[j] = 0;
    if (tid == 0){ s_m = 0; s_cgt = 0; s_tk = 0u; g_ccount[f] = 0; g_fdone[f] = 0; }
    __syncthreads();
    for (int j=tid; j<n; j+=256)
        atomicAdd(&hist[(kmap(g_cbuf[f*CAP + j]) >> 8) & 0xFFF], 1);
    __syncthreads();
    scan_pick<256>(hist, Sc, Sw, R, &sP, &sR, tid);
    int P2 = sP, r2 = sR;

    double acc2 = 0.0;
    for (int j=tid; j<n; j+=256){
        float x = g_cbuf[f*CAP + j];
        int t = (int)((kmap(x) >> 8) & 0xFFF);
        if (t > P2) acc2 += (double)vneg(x);
        else if (t == P2){
            int id = atomicAdd(&s_m, 1);
            if (id < 256) cand2[id] = x;
        }
    }
    __syncthreads();
    int m = s_m; if (m > 256) m = 256;
    if (m > 0){
        for (int j=tid; j<m; j+=256){
            unsigned ki = kmap(cand2[j]);
            int cgt = 0, ceq = 0;
            for (int q=0;q<m;q++){
                unsigned kq = kmap(cand2[q]);
                cgt += (kq > ki); ceq += (kq == ki);
            }
            if (cgt < r2 && r2 <= cgt + ceq) s_tk = ki;   // benign same-value race
        }
        __syncthreads();
        unsigned tk = s_tk;
        int cl = 0;
        for (int j=tid; j<m; j+=256){
            unsigned ki = kmap(cand2[j]);
            if (ki > tk){ acc2 += (double)vneg(cand2[j]); cl++; }
        }
        if (cl) atomicAdd(&s_cgt, cl);
        __syncthreads();
        if (tid == 0) acc2 += (double)(r2 - s_cgt) * (double)vneg(kunmap(tk));
    }

    // block-reduce acc2 -> g_num, then global last-frame finalize
    {
        double r = wredd(acc2);
        if (lane==0) sD[wd] = r;
        __syncthreads();
        if (wd==0){
            double a = (lane<8)? sD[lane] : 0.0;
            a = wredd(a);
            if (lane==0){
                if (a != 0.0) atomicAdd(&g_num, a);
                __threadfence();
                int old = atomicAdd(&g_fin_done, 1);
                s_gl = (old == NFR-1);
            }
        }
    }
    __syncthreads();
    if (s_gl && tid < 32){
        __threadfence();
        int c = (tid < NFR) ? g_pcnt[tid] : 0;
        int cnt = c, den = (tid < NFR) ? 3*(c+1) : 0;
        #pragma unroll
        for (int o=16;o;o>>=1){
            cnt += __shfl_down_sync(0xffffffffu, cnt, o);
            den += __shfl_down_sync(0xffffffffu, den, o);
        }
        if (tid == 0){
            double num  = atomicAdd(&g_num, 0.0);
            double cp   = atomicAdd(&g_clspos, 0.0);
            double hb   = atomicAdd(&g_huber, 0.0);
            double ps   = (double)cnt + 1e-6;
            double clsp = 1.5 * cp / ps;                // ALPHA
            double reg  = 2.0 * hb / ps;                // GAMMA
            double clsn = 1.0 * num / ((double)den + 1e-6); // BETA
            out[0] = (float)(clsp + clsn);  // conf_loss
            out[1] = (float)reg;            // reg_loss
            out[2] = (float)clsp;           // cls_pos_loss
            out[3] = (float)clsn;           // cls_neg_loss
            g_clspos = 0.0; g_huber = 0.0; g_num = 0.0; g_fin_done = 0;
        }
        if (tid < NFR) g_pcnt[tid] = 0;
    }
}

extern "C" void kernel_launch(void* const* d_in, const int* in_sizes, int n_in,
                              void* d_out, int out_size)
{
    const float* rm  = (const float*)d_in[0];
    const float* psm = (const float*)d_in[1];
    const float* pos = (const float*)d_in[2];
    const float* neg = (const float*)d_in[3];
    const float* tgt = (const float*)d_in[4];
    float* out = (float*)d_out;

    k_main<<<(NPOS/2)/256, 256>>>(rm, psm, pos, neg, tgt);   // 275 blocks
    k_scan<<<NFR, 512>>>();
    dim3 gs(SBLK, NFR);            // 69 x 20
    k_sumfin<<<gs, 256>>>(out);
}

// round 14
// speedup vs baseline: 1.6115x; 1.6115x over previous
#include <cuda_runtime.h>
#include <math.h>

// Problem constants
#define BB 4
#define HH 200
#define WW 176
#define HW (HH*WW)         // 35200 = 110*320
#define FA 10
#define NF 5
#define NFR (BB*NF)        // 20 (b,frame) pairs
#define NPF (HW*2)         // 70400 elements per frame
#define NPOS (BB*HW)       // 140800 positions
#define EPSV 1e-6f
#define NB1 2048           // level-1 bins (11-bit key prefix)
#define NB2 4096           // level-2 bins (key bits [9,21))
#define CAP 8192
#define SBLK 69            // blocks per frame in k_sumfin (69*256 >= NPF/4=17600)
#define PLCAP 512
#define TPBM 320

// ---- scratch (device globals; zero-initialized at load; self-cleaning) ----
__device__ float  g_vbuf[BB*NF*NPF];   // masked psm logits, 5.6MB
__device__ int    g_hist[NFR*NB1];     // level-1 histograms
__device__ int    g_pcnt[NFR];
__device__ float  g_cbuf[NFR*CAP];     // threshold-bin candidates
__device__ int    g_ccount[NFR];
__device__ int    g_fdone[NFR];        // per-frame arrival counters
__device__ int    g_Pv[NFR], g_Rv[NFR];
__device__ double g_clspos, g_huber, g_num;
__device__ int    g_fin_done;

// monotonic float<->uint key mapping (ascending)
__device__ __forceinline__ unsigned kmap(float x){
    unsigned u = __float_as_uint(x);
    return (u & 0x80000000u) ? ~u : (u | 0x80000000u);
}
__device__ __forceinline__ float kunmap(unsigned m){
    unsigned u = (m & 0x80000000u) ? (m & 0x7FFFFFFFu) : ~m;
    return __uint_as_float(u);
}
// neg-class loss from raw logit (monotone non-decreasing in x => top-k by x == top-k by v)
__device__ __forceinline__ float vneg(float x){
    float pp = 1.0f/(1.0f + expf(-x));
    return -logf(1.0f - pp + EPSV);
}
__device__ __forceinline__ double wredd(double v){
    #pragma unroll
    for (int o=16;o;o>>=1) v += __shfl_down_sync(0xffffffffu, v, o);
    return v;
}

// hierarchical suffix scan over shared hist[NBINS], T threads.
template<int NBINS, int T>
__device__ __forceinline__ void scan_pick(int* hist, int* Sc, int* Sw,
                                          int k, int* oP, int* oR, int tid)
{
    const int C = NBINS/T;
    const int NW = T/32;
    int s = 0;
    #pragma unroll
    for (int j=0;j<C;j++) s += hist[tid*C + j];
    Sc[tid] = s;
    int ws = s;
    #pragma unroll
    for (int o=16;o;o>>=1) ws += __shfl_down_sync(0xffffffffu, ws, o);
    if ((tid & 31) == 0) Sw[tid >> 5] = ws;
    __syncthreads();
    if (tid == 0){
        int cum = 0, w = NW-1;
        while (w > 0 && cum + Sw[w] < k){ cum += Sw[w]; w--; }
        int c = w*32 + 31;
        while (c > w*32 && cum + Sc[c] < k){ cum += Sc[c]; c--; }
        int b = c*C + C-1;
        while (b > c*C && cum + hist[b] < k){ cum += hist[b]; b--; }
        *oP = b; *oR = k - cum;
    }
    __syncthreads();
}

// ---- main pass: 1 position/thread, grid 440 x 320, block = one batch slice ----
__global__ void __launch_bounds__(TPBM) k_main(
    const float* __restrict__ rm,  const float* __restrict__ psm,
    const float* __restrict__ pos, const float* __restrict__ neg,
    const float* __restrict__ tgt)
{
    __shared__ unsigned sh[NF*NB1];      // 40KB privatized level-1 hist
    __shared__ double sD[10];
    __shared__ int s_pcount;
    __shared__ int s_plist[PLCAP];
    int tid = threadIdx.x;
    int b = blockIdx.x / 110;            // block fully inside one batch
    int pbase = (blockIdx.x - b*110) * TPBM;
    int p = pbase + tid;                 // < HW always (110*320 == HW)
    int g = b*HW + p;

    for (int i=tid; i<NF*NB1; i+=TPBM) sh[i] = 0u;
    if (tid == 0) s_pcount = 0;
    __syncthreads();

    // ---- front-load all 20 independent loads ----
    const float2* pp2 = (const float2*)(pos + (size_t)g*FA);   // 8B aligned
    const float2* nn2 = (const float2*)(neg + (size_t)g*FA);
    float2 pv[5], nv[5];
    #pragma unroll
    for (int j=0;j<5;j++){ pv[j] = pp2[j]; nv[j] = nn2[j]; }
    float xs[FA];
    #pragma unroll
    for (int a=0;a<FA;a++) xs[a] = psm[((size_t)(b*FA + a))*HW + p];

    // ---- masks ----
    unsigned nmask = 0, pmask = 0;
    #pragma unroll
    for (int j=0;j<5;j++){
        if (nv[j].x != 0.0f) nmask |= 1u << (2*j);
        if (nv[j].y != 0.0f) nmask |= 1u << (2*j+1);
        if (pv[j].x != 0.0f) pmask |= 1u << (2*j);
        if (pv[j].y != 0.0f) pmask |= 1u << (2*j+1);
    }

    // ---- shared-hist atomics (contention stays in-block) ----
    #pragma unroll
    for (int a=0;a<FA;a++){
        if ((nmask >> a) & 1u)
            atomicAdd(&sh[((a>>1)<<11) + (kmap(xs[a]) >> 21)], 1u);
    }
    // ---- masked vbuf stores (float2 per frame) ----
    const float QNAN = __int_as_float(0x7FC00000);
    #pragma unroll
    for (int f=0; f<NF; f++){
        float2 w;
        w.x = ((nmask >> (2*f))   & 1u) ? xs[2*f]   : QNAN;
        w.y = ((nmask >> (2*f+1)) & 1u) ? xs[2*f+1] : QNAN;
        *(float2*)(g_vbuf + ((size_t)(b*NF+f))*NPF + (size_t)p*2) = w;
    }
    // ---- append positives to shared list (rare: ~16/block) ----
    unsigned pm = pmask;
    while (pm){
        int a = __ffs(pm) - 1; pm &= pm - 1;
        int id = atomicAdd(&s_pcount, 1);
        if (id < PLCAP) s_plist[id] = (tid << 4) | a;
    }
    __syncthreads();

    // ---- flush nonzero hist bins to global (<=440 adders per address) ----
    for (int i=tid; i<NF*NB1; i+=TPBM){
        unsigned c = sh[i];
        if (c) atomicAdd(&g_hist[b*NF*NB1 + i], (int)c);
    }

    // ---- cooperative positive processing ----
    int cnt = s_pcount; if (cnt > PLCAP) cnt = PLCAP;
    double l_cp = 0.0, l_hb = 0.0;
    for (int e = tid; e < cnt; e += TPBM){
        int pk = s_plist[e];
        int lt = pk >> 4, a = pk & 15;
        int pp = pbase + lt;
        int gg = b*HW + pp;
        atomicAdd(&g_pcnt[b*NF + (a>>1)], 1);
        float x = psm[((size_t)(b*FA + a))*HW + pp];
        float s = 1.0f/(1.0f + expf(-x));
        l_cp -= (double)logf(s + EPSV);
        const float* tp = tgt + ((size_t)gg*(FA*7) + a*7);
        const float* rp = rm  + ((size_t)(b*FA*7) + a*7)*HW + pp;
        #pragma unroll
        for (int j=0;j<7;j++){
            float d = fabsf(rp[(size_t)j*HW] - tp[j]);
            l_hb += (d < 1.0f) ? (double)(0.5f*d*d) : (double)(d - 0.5f);
        }
    }

    // block-reduce the two double sums (10 warps)
    int lane = tid & 31, wd = tid >> 5;
    double r1 = wredd(l_cp);
    if (lane==0) sD[wd] = r1;
    __syncthreads();
    if (wd==0){
        double a = (lane<10)? sD[lane] : 0.0;
        a = wredd(a);
        if (lane==0 && a != 0.0) atomicAdd(&g_clspos, a);
    }
    __syncthreads();
    double r2 = wredd(l_hb);
    if (lane==0) sD[wd] = r2;
    __syncthreads();
    if (wd==0){
        double a = (lane<10)? sD[lane] : 0.0;
        a = wredd(a);
        if (lane==0 && a != 0.0) atomicAdd(&g_huber, a);
    }
}

// ---------------- per-frame threshold pick: 20 x 512 ----------------
__global__ void __launch_bounds__(512) k_scan(){
    __shared__ int hist[NB1];
    __shared__ int Sc[512];
    __shared__ int Sw[16];
    __shared__ int sP, sR;
    int f = blockIdx.x, tid = threadIdx.x;
    for (int i=tid; i<NB1/4; i+=512){
        int4 h = ((const int4*)(g_hist + f*NB1))[i];
        hist[4*i]=h.x; hist[4*i+1]=h.y; hist[4*i+2]=h.z; hist[4*i+3]=h.w;
        ((int4*)(g_hist + f*NB1))[i] = make_int4(0,0,0,0);   // self-clean
    }
    __syncthreads();
    int k = 3*(g_pcnt[f] + 1);                // floor(3*(cnt+1)) exactly
    scan_pick<NB1,512>(hist, Sc, Sw, k, &sP, &sR, tid);
    if (tid == 0){ g_Pv[f] = sP; g_Rv[f] = sR; }
}

// ------- fused plane pass + per-frame last-block refine: grid (SBLK,NFR) x 256 -------
__global__ void __launch_bounds__(256) k_sumfin(float* __restrict__ out){
    __shared__ int hist[NB2];                 // used only by last block of frame
    __shared__ int Sc[256];
    __shared__ int Sw[8];
    __shared__ float cand2[256];
    __shared__ double sD[8];
    __shared__ int sP, sR, s_m, s_cgt, s_last, s_gl;
    __shared__ unsigned s_tk;

    int f = blockIdx.y, tid = threadIdx.x;
    int lane = tid & 31, wd = tid >> 5;
    int P = g_Pv[f];                          // precomputed by k_scan

    // plane pass chunk: sum v(x) above-bin, stash in-bin candidates
    double acc = 0.0;
    int i = blockIdx.x*256 + tid;
    if (i < NPF/4){
        float4 q = ((const float4*)(g_vbuf + (size_t)f*NPF))[i];
        float xv[4] = {q.x, q.y, q.z, q.w};
        #pragma unroll
        for (int j=0;j<4;j++){
            float x = xv[j];
            if (x == x){                        // not NaN => neg==1 anchor
                int t = (int)(kmap(x) >> 21);
                if (t > P) acc += (double)vneg(x);
                else if (t == P){
                    int id = atomicAdd(&g_ccount[f], 1);
                    if (id < CAP) g_cbuf[f*CAP + id] = x;
                }
            }
        }
    }
    {   // block-reduce acc -> g_num, then per-frame arrival
        double r = wredd(acc);
        if (lane==0) sD[wd] = r;
        __syncthreads();
        if (wd==0){
            double a = (lane<8)? sD[lane] : 0.0;
            a = wredd(a);
            if (lane==0){
                if (a != 0.0) atomicAdd(&g_num, a);
                __threadfence();
                int old = atomicAdd(&g_fdone[f], 1);
                s_last = (old == SBLK-1);
            }
        }
    }
    __syncthreads();
    if (!s_last) return;                        // 68 of 69 blocks exit here
    __threadfence();                            // acquire all frame writes

    // ---- last block of frame f: level-2 refinement (key bits [9,21)) ----
    int n = *((volatile int*)&g_ccount[f]); if (n > CAP) n = CAP;
    int R = g_Rv[f];
    for (int j=tid; j<NB2; j+=256) hist[j] = 0;
    if (tid == 0){ s_m = 0; s_cgt = 0; s_tk = 0u; g_ccount[f] = 0; g_fdone[f] = 0; }
    __syncthreads();
    for (int j=tid; j<n; j+=256)
        atomicAdd(&hist[(kmap(g_cbuf[f*CAP + j]) >> 9) & 0xFFF], 1);
    __syncthreads();
    scan_pick<NB2,256>(hist, Sc, Sw, R, &sP, &sR, tid);
    int P2 = sP, r2 = sR;

    double acc2 = 0.0;
    for (int j=tid; j<n; j+=256){
        float x = g_cbuf[f*CAP + j];
        int t = (int)((kmap(x) >> 9) & 0xFFF);
        if (t > P2) acc2 += (double)vneg(x);
        else if (t == P2){
            int id = atomicAdd(&s_m, 1);
            if (id < 256) cand2[id] = x;
        }
    }
    __syncthreads();
    int m = s_m; if (m > 256) m = 256;
    if (m > 0){
        // exact tie-aware finish on tiny candidate set (last 9 key bits)
        for (int j=tid; j<m; j+=256){
            unsigned ki = kmap(cand2[j]);
            int cgt = 0, ceq = 0;
            for (int q=0;q<m;q++){
                unsigned kq = kmap(cand2[q]);
                cgt += (kq > ki); ceq += (kq == ki);
            }
            if (cgt < r2 && r2 <= cgt + ceq) s_tk = ki;   // benign same-value race
        }
        __syncthreads();
        unsigned tk = s_tk;
        int cl = 0;
        for (int j=tid; j<m; j+=256){
            unsigned ki = kmap(cand2[j]);
            if (ki > tk){ acc2 += (double)vneg(cand2[j]); cl++; }
        }
        if (cl) atomicAdd(&s_cgt, cl);
        __syncthreads();
        if (tid == 0) acc2 += (double)(r2 - s_cgt) * (double)vneg(kunmap(tk));
    }

    // block-reduce acc2 -> g_num, then global last-frame finalize
    {
        double r = wredd(acc2);
        if (lane==0) sD[wd] = r;
        __syncthreads();
        if (wd==0){
            double a = (lane<8)? sD[lane] : 0.0;
            a = wredd(a);
            if (lane==0){
                if (a != 0.0) atomicAdd(&g_num, a);
                __threadfence();
                int old = atomicAdd(&g_fin_done, 1);
                s_gl = (old == NFR-1);
            }
        }
    }
    __syncthreads();
    if (s_gl && tid < 32){
        __threadfence();
        int c = (tid < NFR) ? g_pcnt[tid] : 0;
        int cnt = c, den = (tid < NFR) ? 3*(c+1) : 0;
        #pragma unroll
        for (int o=16;o;o>>=1){
            cnt += __shfl_down_sync(0xffffffffu, cnt, o);
            den += __shfl_down_sync(0xffffffffu, den, o);
        }
        if (tid == 0){
            double num  = atomicAdd(&g_num, 0.0);
            double cp   = atomicAdd(&g_clspos, 0.0);
            double hb   = atomicAdd(&g_huber, 0.0);
            double ps   = (double)cnt + 1e-6;
            double clsp = 1.5 * cp / ps;                // ALPHA
            double reg  = 2.0 * hb / ps;                // GAMMA
            double clsn = 1.0 * num / ((double)den + 1e-6); // BETA
            out[0] = (float)(clsp + clsn);  // conf_loss
            out[1] = (float)reg;            // reg_loss
            out[2] = (float)clsp;           // cls_pos_loss
            out[3] = (float)clsn;           // cls_neg_loss
            g_clspos = 0.0; g_huber = 0.0; g_num = 0.0; g_fin_done = 0;
        }
        if (tid < NFR) g_pcnt[tid] = 0;
    }
}

extern "C" void kernel_launch(void* const* d_in, const int* in_sizes, int n_in,
                              void* d_out, int out_size)
{
    const float* rm  = (const float*)d_in[0];
    const float* psm = (const float*)d_in[1];
    const float* pos = (const float*)d_in[2];
    const float* neg = (const float*)d_in[3];
    const float* tgt = (const float*)d_in[4];
    float* out = (float*)d_out;

    k_main<<<BB*110, TPBM>>>(rm, psm, pos, neg, tgt);   // 440 blocks, batch-aligned
    k_scan<<<NFR, 512>>>();
    dim3 gs(SBLK, NFR);            // 69 x 20
    k_sumfin<<<gs, 256>>>(out);
}